// round 13
// baseline (speedup 1.0000x reference)
#include <cuda_runtime.h>
#include <math.h>

// ---------------------------------------------------------------------------
// EncoderRNN (2-layer, 2-"direction" forward GRU): B=64, T=1024, I=64, H=256
//
// Only W_hh @ h is time-sequential. Phases:
//   A: k_gi0  — gi0[t,d,b,g] = W_ih0 @ x_t + b_ih0          (one parallel GEMM)
//   B: k_rec  — layer-0 recurrence, PERSISTENT kernel, software barriers,
//               W_hh held in smem for all 1024 steps; h0 full history stored
//   C: k_gi1  — gi1[t,d,b,g] = W_ih1 @ concat(h0[t]) + b_ih1 (one parallel GEMM,
//               register-prefetch pipelined over 8 K-chunks)
//   D: k_rec  — layer-1 recurrence (same persistent kernel), writes d_out at
//               t == clip(seq_len[b]-1, 0, T-1)
//
// Dot-product cores use PACKED fp32 FMA (fma.rn.f32x2, the B300 FFMA2 path
// ptxas never emits from C++): float4 smem loads reinterpreted as ulonglong2,
// one u64 accumulator = two fp32 partial sums, horizontal add at the end.
// Exact fp32 FMA per lane — only the summation order splits even/odd.
//
// Barrier structure: CTA (d, js, bg) only consumes h produced by CTAs with the
// SAME (d, bg) — 4 independent 32-CTA barriers, 128B-padded counters.
// Hs staging is double-buffered (1 __syncthreads per 64-K chunk).
// Gate nonlinearities: HW approx (tanh.approx / MUFU.EX2+RCP, err ~1e-5).
// ---------------------------------------------------------------------------

#define TT 1024
#define BB 64
#define HH 256
#define NB 128   // CTAs per persistent recurrence kernel. 1 CTA/SM always fits
                 // (8 warps, 42.4KB smem), NB <= 148 SMs, nothing co-resident
                 // -> all barrier participants provably co-resident.
#define GRP 32   // CTAs per barrier group (same direction + batch-half)

typedef unsigned long long u64t;

// __device__ scratch (allocation-free rule: static device globals only)
__device__ float g_gi0[(size_t)TT * 2 * BB * 768];   // 402.7 MB
__device__ float g_gi1[(size_t)TT * 2 * BB * 768];   // 402.7 MB
__device__ float g_h0 [(size_t)TT * 2 * BB * HH];    // 134.2 MB (full history)
__device__ float g_h1 [(size_t)TT * 2 * BB * HH];    // 134.2 MB (full history)
// Barrier counters: [layer][group], each padded to 128B (own LTS line).
__device__ unsigned g_cnt[2][4][32];

__global__ void k_init() {                            // graph-replay reset
    if (threadIdx.x < 8) g_cnt[threadIdx.x >> 2][threadIdx.x & 3][0] = 0u;
}

// Packed fp32 FMA: d.lo += a.lo*b.lo, d.hi += a.hi*b.hi (exact FFMA per lane).
__device__ __forceinline__ void ffma2(u64t& d, u64t a, u64t b) {
    asm("fma.rn.f32x2 %0, %1, %2, %0;" : "+l"(d) : "l"(a), "l"(b));
}
// Horizontal sum of a packed pair.
__device__ __forceinline__ float hsum2(u64t v) {
    return __uint_as_float((unsigned)v) + __uint_as_float((unsigned)(v >> 32));
}

// Fast gate nonlinearities (HW MUFU paths, on the serial critical path).
__device__ __forceinline__ float sigmoidf_(float v) {
    return __fdividef(1.0f, 1.0f + __expf(-v));      // MUFU.EX2 + MUFU.RCP
}
__device__ __forceinline__ float tanhf_(float v) {
    float r;
    asm("tanh.approx.f32 %0, %1;" : "=f"(r) : "f"(v));
    return r;
}

__device__ __forceinline__ unsigned ld_acq(const unsigned* p) {
    unsigned v;
    asm volatile("ld.acquire.gpu.u32 %0, [%1];" : "=r"(v) : "l"(p) : "memory");
    return v;
}

// Software group barrier: monotonic counter. Release = red.release (orders the
// preceding stcg h-stores); acquire = ld.acquire.gpu spin with nanosleep
// backoff (keeps spinning SMs off the LTS while late CTAs stream h chunks).
__device__ __forceinline__ void group_bar(unsigned* cnt, unsigned target) {
    __syncthreads();
    if (threadIdx.x == 0) {
        asm volatile("red.release.gpu.add.u32 [%0], %1;"
                     :: "l"(cnt), "r"(1u) : "memory");
        while (ld_acq(cnt) < target) {
            asm volatile("nanosleep.u32 64;");
        }
    }
    __syncthreads();
}

// ---------------------------------------------------------------------------
// Phase A: gi0. grid = (1024, 32): x=t; y: d = y>>4, nt = y&15.
// CTA: out[64 b][48 rows] (3 gates x 16 hidden cols), K=64 (single chunk).
// thread: jj = tid&15 (hidden col), bq = tid>>4 (4 batches) -> 12 accumulators
// ---------------------------------------------------------------------------
__global__ __launch_bounds__(256) void k_gi0(const float* __restrict__ x,
                                             const float* __restrict__ Wih0,
                                             const float* __restrict__ bih0)
{
    __shared__ float Ws[48 * 68];
    __shared__ float Us[64 * 68];
    const int t  = blockIdx.x;
    const int d  = blockIdx.y >> 4;
    const int nt = blockIdx.y & 15;
    const int tid = threadIdx.x;
    const int jj = tid & 15, bq = tid >> 4;

#pragma unroll
    for (int i = 0; i < 3; i++) {
        int idx = i * 256 + tid;
        int r = idx >> 4, q = idx & 15;
        int grow = (r >> 4) * 256 + nt * 16 + (r & 15);
        *(float4*)(Ws + r * 68 + q * 4) =
            *(const float4*)(Wih0 + ((size_t)(d * 768 + grow)) * 64 + q * 4);
    }
#pragma unroll
    for (int i = 0; i < 4; i++) {
        int idx = i * 256 + tid;
        int bb = idx >> 4, q = idx & 15;
        *(float4*)(Us + bb * 68 + q * 4) =
            *(const float4*)(x + ((size_t)bb * TT + t) * 64 + q * 4);
    }
    __syncthreads();

    u64t acc[3][4];
#pragma unroll
    for (int g = 0; g < 3; g++)
#pragma unroll
        for (int i = 0; i < 4; i++) acc[g][i] = 0ull;

#pragma unroll
    for (int k4 = 0; k4 < 16; k4++) {
        ulonglong2 w0 = *(const ulonglong2*)(Ws + (jj) * 68 + k4 * 4);
        ulonglong2 w1 = *(const ulonglong2*)(Ws + (16 + jj) * 68 + k4 * 4);
        ulonglong2 w2 = *(const ulonglong2*)(Ws + (32 + jj) * 68 + k4 * 4);
#pragma unroll
        for (int i = 0; i < 4; i++) {
            ulonglong2 u = *(const ulonglong2*)(Us + (bq * 4 + i) * 68 + k4 * 4);
            ffma2(acc[0][i], u.x, w0.x); ffma2(acc[0][i], u.y, w0.y);
            ffma2(acc[1][i], u.x, w1.x); ffma2(acc[1][i], u.y, w1.y);
            ffma2(acc[2][i], u.x, w2.x); ffma2(acc[2][i], u.y, w2.y);
        }
    }

#pragma unroll
    for (int g = 0; g < 3; g++) {
        int row = g * 256 + nt * 16 + jj;
        float bias = bih0[d * 768 + row];
#pragma unroll
        for (int i = 0; i < 4; i++) {
            int b = bq * 4 + i;
            g_gi0[(((size_t)t * 2 + d) * BB + b) * 768 + row] = hsum2(acc[g][i]) + bias;
        }
    }
}

// ---------------------------------------------------------------------------
// Phase C: gi1. Same tile, K=512 (concat of both dirs of h0[t]) in 8 chunks
// of 64 (chunks 0..3 -> dir0, 4..7 -> dir1). Register-prefetch pipeline:
// LDG for chunk c+1 issued into regs while computing chunk c from smem.
// ---------------------------------------------------------------------------
__global__ __launch_bounds__(256) void k_gi1(const float* __restrict__ Wih1,
                                             const float* __restrict__ bih1)
{
    __shared__ float Ws[48 * 68];
    __shared__ float Us[64 * 68];
    const int t  = blockIdx.x;
    const int d  = blockIdx.y >> 4;
    const int nt = blockIdx.y & 15;
    const int tid = threadIdx.x;
    const int jj = tid & 15, bq = tid >> 4;

    u64t acc[3][4];
#pragma unroll
    for (int g = 0; g < 3; g++)
#pragma unroll
        for (int i = 0; i < 4; i++) acc[g][i] = 0ull;

    float4 wreg[3], ureg[4];
    // prefetch chunk 0 (dir 0, koff 0)
#pragma unroll
    for (int i = 0; i < 3; i++) {
        int idx = i * 256 + tid;
        int r = idx >> 4, q = idx & 15;
        int grow = (r >> 4) * 256 + nt * 16 + (r & 15);
        wreg[i] = *(const float4*)(Wih1 + ((size_t)(d * 768 + grow)) * 512 + q * 4);
    }
#pragma unroll
    for (int i = 0; i < 4; i++) {
        int idx = i * 256 + tid;
        int bb = idx >> 4, q = idx & 15;
        ureg[i] = *(const float4*)(g_h0 + (((size_t)t * 2 + 0) * BB + bb) * HH + q * 4);
    }

    for (int c = 0; c < 8; c++) {
        __syncthreads();            // previous chunk's compute fully done
#pragma unroll
        for (int i = 0; i < 3; i++) {
            int idx = i * 256 + tid;
            int r = idx >> 4, q = idx & 15;
            *(float4*)(Ws + r * 68 + q * 4) = wreg[i];
        }
#pragma unroll
        for (int i = 0; i < 4; i++) {
            int idx = i * 256 + tid;
            int bb = idx >> 4, q = idx & 15;
            *(float4*)(Us + bb * 68 + q * 4) = ureg[i];
        }
        __syncthreads();
        if (c < 7) {                // prefetch next chunk; overlaps compute below
            const int cn = c + 1;
            const int dd = cn >> 2;
            const int koff = (cn & 3) * 64;
#pragma unroll
            for (int i = 0; i < 3; i++) {
                int idx = i * 256 + tid;
                int r = idx >> 4, q = idx & 15;
                int grow = (r >> 4) * 256 + nt * 16 + (r & 15);
                wreg[i] = *(const float4*)(Wih1 +
                            ((size_t)(d * 768 + grow)) * 512 + cn * 64 + q * 4);
            }
#pragma unroll
            for (int i = 0; i < 4; i++) {
                int idx = i * 256 + tid;
                int bb = idx >> 4, q = idx & 15;
                ureg[i] = *(const float4*)(g_h0 +
                            (((size_t)t * 2 + dd) * BB + bb) * HH + koff + q * 4);
            }
        }
#pragma unroll
        for (int k4 = 0; k4 < 16; k4++) {
            ulonglong2 w0 = *(const ulonglong2*)(Ws + (jj) * 68 + k4 * 4);
            ulonglong2 w1 = *(const ulonglong2*)(Ws + (16 + jj) * 68 + k4 * 4);
            ulonglong2 w2 = *(const ulonglong2*)(Ws + (32 + jj) * 68 + k4 * 4);
#pragma unroll
            for (int i = 0; i < 4; i++) {
                ulonglong2 u = *(const ulonglong2*)(Us + (bq * 4 + i) * 68 + k4 * 4);
                ffma2(acc[0][i], u.x, w0.x); ffma2(acc[0][i], u.y, w0.y);
                ffma2(acc[1][i], u.x, w1.x); ffma2(acc[1][i], u.y, w1.y);
                ffma2(acc[2][i], u.x, w2.x); ffma2(acc[2][i], u.y, w2.y);
            }
        }
    }

#pragma unroll
    for (int g = 0; g < 3; g++) {
        int row = g * 256 + nt * 16 + jj;
        float bias = bih1[d * 768 + row];
#pragma unroll
        for (int i = 0; i < 4; i++) {
            int b = bq * 4 + i;
            g_gi1[(((size_t)t * 2 + d) * BB + b) * 768 + row] = hsum2(acc[g][i]) + bias;
        }
    }
}

// ---------------------------------------------------------------------------
// Phases B/D: PERSISTENT recurrence kernel (shared by both layers).
// Grid = 128 CTAs: d = bid>>6; js = (bid&63)>>1 (32 j-slices of 8);
// bg = bid&1 (2 batch halves of 32). Thread: jj = tid&7, bl = tid>>3.
// Each thread owns one (b, j) for ALL timesteps -> h(t-1)[b,j] stays in a reg.
// W_hh tile (24 rows x 256 K, stride 260, conflict-free float4 LDS) loaded
// into smem ONCE. Per step: h(t-1) staged in 4 64-K chunks into DOUBLE-
// BUFFERED Hs (one sync per chunk), packed-FMA dot products, gate math,
// stcg h(t) store, gi(t+1) prefetched BEFORE the 32-CTA GROUP barrier.
// ---------------------------------------------------------------------------
__global__ __launch_bounds__(256) void k_rec(const float* __restrict__ Whh,
                                             const float* __restrict__ bhh,
                                             int layer,
                                             const int* __restrict__ seq,
                                             float* __restrict__ out)
{
    __shared__ float Ws[24 * 260];      // 24,960 B, full K=256 resident
    __shared__ float Hs[2][32 * 68];    // 2 x 8,704 B, ping-pong 64-K chunks

    const float*  gi   = layer ? g_gi1 : g_gi0;
    float*        hbuf = layer ? g_h1  : g_h0;

    const int bid = blockIdx.x;
    const int d   = bid >> 6;
    const int rem = bid & 63;
    const int js  = rem >> 1;
    const int bg  = rem & 1;
    const int tid = threadIdx.x;
    const int jj  = tid & 7, bl = tid >> 3;
    const int b   = bg * 32 + bl;
    const int j   = js * 8 + jj;

    unsigned* cnt = &g_cnt[layer][d * 2 + bg][0];   // this CTA's barrier group

    // Load W_hh tile once: 24 rows (3 gates x 8 cols) x 256 K = 1536 float4.
#pragma unroll
    for (int i = 0; i < 6; i++) {
        int idx = i * 256 + tid;
        int r = idx >> 6, q = idx & 63;
        int grow = (r >> 3) * 256 + js * 8 + (r & 7);
        *(float4*)(Ws + r * 260 + q * 4) =
            *(const float4*)(Whh + ((size_t)(d * 768 + grow)) * HH + q * 4);
    }
    const float bhr = bhh[d * 768 + j];
    const float bhz = bhh[d * 768 + 256 + j];
    const float bhn = bhh[d * 768 + 512 + j];
    int cap = -1;
    if (out) {
        int s = seq[b] - 1;
        cap = s < 0 ? 0 : (s > TT - 1 ? TT - 1 : s);
    }
    __syncthreads();

    const int i0b = tid >> 4,          i0q = tid & 15;          // staging slot 0
    const int i1b = (256 + tid) >> 4,  i1q = (256 + tid) & 15;  // staging slot 1

    const size_t gstep = (size_t)2 * BB * 768;                  // gi stride per t
    const float* gp = gi + ((size_t)d * BB + b) * 768;          // t = 0
    float ir  = __ldcg(gp + j);                                 // prefetch t = 0
    float iz  = __ldcg(gp + 256 + j);
    float in_ = __ldcg(gp + 512 + j);

    float hprev = 0.0f;
    for (int t = 0; t < TT; t++) {
        u64t ar2 = 0ull, az2 = 0ull, an2 = 0ull;
        if (t > 0) {
            const float* hsrc = hbuf + (((size_t)(t - 1) * 2 + d) * BB + bg * 32) * HH;
            float4 pre0 = __ldcg((const float4*)(hsrc + (size_t)i0b * HH + i0q * 4));
            float4 pre1 = __ldcg((const float4*)(hsrc + (size_t)i1b * HH + i1q * 4));
#pragma unroll
            for (int c = 0; c < 4; c++) {
                float* hb = Hs[c & 1];
                *(float4*)(hb + i0b * 68 + i0q * 4) = pre0;
                *(float4*)(hb + i1b * 68 + i1q * 4) = pre1;
                __syncthreads();   // hb fully staged; also (for c>=2) this is
                                   // the barrier separating the previous reads
                                   // of hb from the store above
                if (c < 3) {       // prefetch next chunk; overlaps compute
                    pre0 = __ldcg((const float4*)(hsrc + (size_t)i0b * HH +
                                                  (c + 1) * 64 + i0q * 4));
                    pre1 = __ldcg((const float4*)(hsrc + (size_t)i1b * HH +
                                                  (c + 1) * 64 + i1q * 4));
                }
                const float* wc = Ws + c * 64;
#pragma unroll
                for (int k4 = 0; k4 < 16; k4++) {
                    ulonglong2 h  = *(const ulonglong2*)(hb + bl * 68 + k4 * 4);
                    ulonglong2 w0 = *(const ulonglong2*)(wc + (jj) * 260 + k4 * 4);
                    ulonglong2 w1 = *(const ulonglong2*)(wc + (8 + jj) * 260 + k4 * 4);
                    ulonglong2 w2 = *(const ulonglong2*)(wc + (16 + jj) * 260 + k4 * 4);
                    ffma2(ar2, h.x, w0.x); ffma2(ar2, h.y, w0.y);
                    ffma2(az2, h.x, w1.x); ffma2(az2, h.y, w1.y);
                    ffma2(an2, h.x, w2.x); ffma2(an2, h.y, w2.y);
                }
                // no trailing sync: next chunk writes the OTHER buffer; the
                // chunk after that is separated from these reads by the next
                // iteration's __syncthreads.
            }
        }
        const float ar = hsum2(ar2), az = hsum2(az2), an = hsum2(an2);

        const float r = sigmoidf_(ir + ar + bhr);
        const float z = sigmoidf_(iz + az + bhz);
        const float n = tanhf_(in_ + r * (an + bhn));
        const float hnew = (1.0f - z) * n + z * hprev;
        hprev = hnew;
        __stcg(&hbuf[(((size_t)t * 2 + d) * BB + b) * HH + j], hnew);
        if (out && cap == t) out[(size_t)b * 512 + d * 256 + j] = hnew;

        if (t < TT - 1) {
            // Prefetch gi(t+1) BEFORE the barrier: gi is fully precomputed by
            // a prior kernel, so the LDG latency overlaps the barrier spin.
            gp += gstep;
            ir  = __ldcg(gp + j);
            iz  = __ldcg(gp + 256 + j);
            in_ = __ldcg(gp + 512 + j);
            group_bar(cnt, (unsigned)(t + 1) * GRP);
        }
    }
}

// ---------------------------------------------------------------------------
// Host launcher: graph-capturable (kernel launches only).
// Inputs (metadata order): input_tensor, W_ih0, W_hh0, b_ih0, b_hh0,
//                          W_ih1, W_hh1, b_ih1, b_hh1, seq_len
// ---------------------------------------------------------------------------
extern "C" void kernel_launch(void* const* d_in, const int* in_sizes, int n_in,
                              void* d_out, int out_size)
{
    (void)in_sizes; (void)n_in; (void)out_size;
    const float* x    = (const float*)d_in[0];
    const float* Wih0 = (const float*)d_in[1];
    const float* Whh0 = (const float*)d_in[2];
    const float* bih0 = (const float*)d_in[3];
    const float* bhh0 = (const float*)d_in[4];
    const float* Wih1 = (const float*)d_in[5];
    const float* Whh1 = (const float*)d_in[6];
    const float* bih1 = (const float*)d_in[7];
    const float* bhh1 = (const float*)d_in[8];
    const int*   seq  = (const int*)d_in[9];
    float* out = (float*)d_out;

    k_init<<<1, 32>>>();                                   // reset barrier counters
    k_gi0<<<dim3(TT, 32), 256>>>(x, Wih0, bih0);           // Phase A
    k_rec<<<NB, 256>>>(Whh0, bhh0, 0, seq, (float*)0);     // Phase B (layer 0)
    k_gi1<<<dim3(TT, 32), 256>>>(Wih1, bih1);              // Phase C
    k_rec<<<NB, 256>>>(Whh1, bhh1, 1, seq, out);           // Phase D (layer 1)
}

// round 15
// speedup vs baseline: 1.4006x; 1.4006x over previous
#include <cuda_runtime.h>
#include <math.h>

// ---------------------------------------------------------------------------
// EncoderRNN (2-layer, 2-"direction" forward GRU): B=64, T=1024, I=64, H=256
//
// Round-15 = Round-14 architecture with ONE fix: k_rec's Hs row stride
// 264 -> 288. The 264 stride let the per-row skew (up to 24 floats) overlap
// the next row at the skew-wrap boundary (b=15/16), racing 16 floats of h
// per step -> rel_err 2.2e-2. Stride 288 gives 32 floats of pad >= max skew.
//
//   k_rec: thread tile 3 gates x 4 batches x K/4 (kh split) + smem reduction
//   k_gi1: tile 3 gates x 32 jcols x 64 b per CTA, 8 batches per thread
// Phases A-D, group barriers, packed FFMA2, approx gates: as Round 13/14.
// ---------------------------------------------------------------------------

#define TT 1024
#define BB 64
#define HH 256
#define NB 128   // persistent CTAs; <=148 SMs, co-resident by construction
#define GRP 32   // CTAs per barrier group (same direction + batch-half)

typedef unsigned long long u64t;

// k_rec dynamic smem partition (floats)
#define WS_F   (24 * 260)          // W tile, row stride 260 (4-float pad)
#define HS_F   (32 * 288 + 32)     // h tile, stride 288: 256 data + 32 pad >= skew 24
#define RS_F   (4 * 64 * 12)       // kh-partial reduction pane
#define SMEM_REC_BYTES ((WS_F + HS_F + RS_F) * 4)

// __device__ scratch (allocation-free rule: static device globals only)
__device__ float g_gi0[(size_t)TT * 2 * BB * 768];   // 402.7 MB
__device__ float g_gi1[(size_t)TT * 2 * BB * 768];   // 402.7 MB
__device__ float g_h0 [(size_t)TT * 2 * BB * HH];    // 134.2 MB
__device__ float g_h1 [(size_t)TT * 2 * BB * HH];    // 134.2 MB
__device__ unsigned g_cnt[2][4][32];                 // 128B-padded counters

__global__ void k_init() {                            // graph-replay reset
    if (threadIdx.x < 8) g_cnt[threadIdx.x >> 2][threadIdx.x & 3][0] = 0u;
}

// Packed fp32 FMA (B300 FFMA2 path; exact FFMA per lane).
__device__ __forceinline__ void ffma2(u64t& d, u64t a, u64t b) {
    asm("fma.rn.f32x2 %0, %1, %2, %0;" : "+l"(d) : "l"(a), "l"(b));
}
__device__ __forceinline__ float hsum2(u64t v) {
    return __uint_as_float((unsigned)v) + __uint_as_float((unsigned)(v >> 32));
}

__device__ __forceinline__ float sigmoidf_(float v) {
    return __fdividef(1.0f, 1.0f + __expf(-v));      // MUFU.EX2 + MUFU.RCP
}
__device__ __forceinline__ float tanhf_(float v) {
    float r;
    asm("tanh.approx.f32 %0, %1;" : "=f"(r) : "f"(v));
    return r;
}

__device__ __forceinline__ unsigned ld_acq(const unsigned* p) {
    unsigned v;
    asm volatile("ld.acquire.gpu.u32 %0, [%1];" : "=r"(v) : "l"(p) : "memory");
    return v;
}

// Software group barrier (release REDG / acquire-spin), validated R13.
__device__ __forceinline__ void group_bar(unsigned* cnt, unsigned target) {
    __syncthreads();
    if (threadIdx.x == 0) {
        asm volatile("red.release.gpu.add.u32 [%0], %1;"
                     :: "l"(cnt), "r"(1u) : "memory");
        while (ld_acq(cnt) < target) {
            asm volatile("nanosleep.u32 64;");
        }
    }
    __syncthreads();
}

// ---------------------------------------------------------------------------
// Phase A: gi0 (K=64, small — unchanged from the passing Round-13 version).
// ---------------------------------------------------------------------------
__global__ __launch_bounds__(256) void k_gi0(const float* __restrict__ x,
                                             const float* __restrict__ Wih0,
                                             const float* __restrict__ bih0)
{
    __shared__ float Ws[48 * 68];
    __shared__ float Us[64 * 68];
    const int t  = blockIdx.x;
    const int d  = blockIdx.y >> 4;
    const int nt = blockIdx.y & 15;
    const int tid = threadIdx.x;
    const int jj = tid & 15, bq = tid >> 4;

#pragma unroll
    for (int i = 0; i < 3; i++) {
        int idx = i * 256 + tid;
        int r = idx >> 4, q = idx & 15;
        int grow = (r >> 4) * 256 + nt * 16 + (r & 15);
        *(float4*)(Ws + r * 68 + q * 4) =
            *(const float4*)(Wih0 + ((size_t)(d * 768 + grow)) * 64 + q * 4);
    }
#pragma unroll
    for (int i = 0; i < 4; i++) {
        int idx = i * 256 + tid;
        int bb = idx >> 4, q = idx & 15;
        *(float4*)(Us + bb * 68 + q * 4) =
            *(const float4*)(x + ((size_t)bb * TT + t) * 64 + q * 4);
    }
    __syncthreads();

    u64t acc[3][4];
#pragma unroll
    for (int g = 0; g < 3; g++)
#pragma unroll
        for (int i = 0; i < 4; i++) acc[g][i] = 0ull;

#pragma unroll
    for (int k4 = 0; k4 < 16; k4++) {
        ulonglong2 w0 = *(const ulonglong2*)(Ws + (jj) * 68 + k4 * 4);
        ulonglong2 w1 = *(const ulonglong2*)(Ws + (16 + jj) * 68 + k4 * 4);
        ulonglong2 w2 = *(const ulonglong2*)(Ws + (32 + jj) * 68 + k4 * 4);
#pragma unroll
        for (int i = 0; i < 4; i++) {
            ulonglong2 u = *(const ulonglong2*)(Us + (bq * 4 + i) * 68 + k4 * 4);
            ffma2(acc[0][i], u.x, w0.x); ffma2(acc[0][i], u.y, w0.y);
            ffma2(acc[1][i], u.x, w1.x); ffma2(acc[1][i], u.y, w1.y);
            ffma2(acc[2][i], u.x, w2.x); ffma2(acc[2][i], u.y, w2.y);
        }
    }

#pragma unroll
    for (int g = 0; g < 3; g++) {
        int row = g * 256 + nt * 16 + jj;
        float bias = bih0[d * 768 + row];
#pragma unroll
        for (int i = 0; i < 4; i++) {
            int b = bq * 4 + i;
            g_gi0[(((size_t)t * 2 + d) * BB + b) * 768 + row] = hsum2(acc[g][i]) + bias;
        }
    }
}

// ---------------------------------------------------------------------------
// Phase C: gi1. grid (1024, 16): d = y>>3, nt = y&7 (8 col-groups of 32 j).
// CTA tile: 96 rows (3g x 32 j) x 64 b, K=512 in 8 chunks of 64 (0-3 dir0,
// 4-7 dir1). Thread (jj = tid&31, bq = tid>>5): 3 rows x 8 batches.
// Us skew ((b>>3)&7)*4 is overlap-safe: stride 68 = 64 data + 4 pad, skew
// increases monotonically (+4) across every group boundary inside b<64.
// ---------------------------------------------------------------------------
__global__ __launch_bounds__(256) void k_gi1(const float* __restrict__ Wih1,
                                             const float* __restrict__ bih1)
{
    __shared__ float Ws[96 * 68];        // 26,112 B
    __shared__ float Us[64 * 68 + 32];   // 17,536 B (skew room)
    const int t  = blockIdx.x;
    const int d  = blockIdx.y >> 3;
    const int nt = blockIdx.y & 7;
    const int tid = threadIdx.x;
    const int jj = tid & 31, bq = tid >> 5;

    u64t acc[3][8];
#pragma unroll
    for (int g = 0; g < 3; g++)
#pragma unroll
        for (int i = 0; i < 8; i++) acc[g][i] = 0ull;

    for (int c = 0; c < 8; c++) {
        __syncthreads();                 // previous chunk's reads done
#pragma unroll
        for (int q = 0; q < 6; q++) {
            int idx = q * 256 + tid;
            int r = idx >> 4, q4 = idx & 15;
            int grow = (r >> 5) * 256 + nt * 32 + (r & 31);
            *(float4*)(Ws + r * 68 + q4 * 4) =
                *(const float4*)(Wih1 + ((size_t)(d * 768 + grow)) * 512 + c * 64 + q4 * 4);
        }
        const int dd = c >> 2;
        const int koff = (c & 3) * 64;
#pragma unroll
        for (int q = 0; q < 4; q++) {
            int idx = q * 256 + tid;
            int b = idx >> 4, k4 = idx & 15;
            *(float4*)(Us + b * 68 + ((b >> 3) & 7) * 4 + k4 * 4) =
                *(const float4*)(g_h0 + (((size_t)t * 2 + dd) * BB + b) * HH + koff + k4 * 4);
        }
        __syncthreads();
#pragma unroll
        for (int k4 = 0; k4 < 16; k4++) {
            ulonglong2 w0 = *(const ulonglong2*)(Ws + (jj) * 68 + k4 * 4);
            ulonglong2 w1 = *(const ulonglong2*)(Ws + (32 + jj) * 68 + k4 * 4);
            ulonglong2 w2 = *(const ulonglong2*)(Ws + (64 + jj) * 68 + k4 * 4);
#pragma unroll
            for (int i = 0; i < 8; i++) {
                int b = bq * 8 + i;
                ulonglong2 u = *(const ulonglong2*)(Us + b * 68 + ((b >> 3) & 7) * 4 + k4 * 4);
                ffma2(acc[0][i], u.x, w0.x); ffma2(acc[0][i], u.y, w0.y);
                ffma2(acc[1][i], u.x, w1.x); ffma2(acc[1][i], u.y, w1.y);
                ffma2(acc[2][i], u.x, w2.x); ffma2(acc[2][i], u.y, w2.y);
            }
        }
    }

#pragma unroll
    for (int g = 0; g < 3; g++) {
        int row = g * 256 + nt * 32 + jj;
        float bias = bih1[d * 768 + row];
#pragma unroll
        for (int i = 0; i < 8; i++) {
            int b = bq * 8 + i;
            g_gi1[(((size_t)t * 2 + d) * BB + b) * 768 + row] = hsum2(acc[g][i]) + bias;
        }
    }
}

// ---------------------------------------------------------------------------
// Phases B/D: PERSISTENT recurrence, kh-split tile.
// Grid 128: d = bid>>6, js = (bid&63)>>1 (8-j slice), bg = bid&1.
// Thread: jj = tid&7, bq = (tid>>3)&7, kh = tid>>6. Each thread: 3 gate rows
// x 4 batches x K/4 quarter. Full h(t-1) 32x256 tile staged per step into Hs
// (stride 288: 256 data + 32 pad >= max skew 24 -> NO row overlap, fixing the
// R14 race at b=15/16). Cross-kh reduction via Rs; owners (tid<64) do gate
// math, stcg h-store, out-capture, gi(t+1) prefetch. 32-CTA group barrier.
// Dynamic smem 74.2KB -> 1 CTA/SM.
// ---------------------------------------------------------------------------
__global__ __launch_bounds__(256) void k_rec(const float* __restrict__ Whh,
                                             const float* __restrict__ bhh,
                                             int layer,
                                             const int* __restrict__ seq,
                                             float* __restrict__ out)
{
    extern __shared__ float sm[];
    float* Ws = sm;                      // 24 x 260
    float* Hs = sm + WS_F;               // 32 rows, stride 288 + skew
    float* Rs = sm + WS_F + HS_F;        // [kh][slot][12]

    const float* gi   = layer ? g_gi1 : g_gi0;
    float*       hbuf = layer ? g_h1  : g_h0;

    const int bid = blockIdx.x;
    const int d   = bid >> 6;
    const int rem = bid & 63;
    const int js  = rem >> 1;
    const int bg  = rem & 1;
    const int tid = threadIdx.x;
    const int jj  = tid & 7;
    const int bq  = (tid >> 3) & 7;
    const int kh  = tid >> 6;
    const int slot = tid & 63;
    const int j   = js * 8 + jj;
    const bool owner = (tid < 64);       // kh == 0
    const int b0  = bg * 32 + bq * 4;    // owner's first batch

    unsigned* cnt = &g_cnt[layer][d * 2 + bg][0];

    // W tile once: 24 rows (3 gates x 8 j) x 256 K, stride 260.
#pragma unroll
    for (int i = 0; i < 6; i++) {
        int idx = i * 256 + tid;
        int r = idx >> 6, q = idx & 63;
        int grow = (r >> 3) * 256 + js * 8 + (r & 7);
        *(float4*)(Ws + r * 260 + q * 4) =
            *(const float4*)(Whh + ((size_t)(d * 768 + grow)) * HH + q * 4);
    }

    float bhr = 0.f, bhz = 0.f, bhn = 0.f;
    float hprev[4] = {0.f, 0.f, 0.f, 0.f};
    float ir[4], iz[4], in_[4];
    int cap[4] = {-1, -1, -1, -1};
    if (owner) {
        bhr = bhh[d * 768 + j];
        bhz = bhh[d * 768 + 256 + j];
        bhn = bhh[d * 768 + 512 + j];
#pragma unroll
        for (int i = 0; i < 4; i++) {
            if (out) {
                int s = seq[b0 + i] - 1;
                cap[i] = s < 0 ? 0 : (s > TT - 1 ? TT - 1 : s);
            }
            const float* gp = gi + (((size_t)d) * BB + b0 + i) * 768;  // t = 0
            ir[i] = __ldcg(gp + j);
            iz[i] = __ldcg(gp + 256 + j);
            in_[i] = __ldcg(gp + 512 + j);
        }
    }
    __syncthreads();

    for (int t = 0; t < TT; t++) {
        float p[12];
        if (t > 0) {
            // stage full h(t-1) 32x256 (8 f4 per thread)
            const float* hsrc = hbuf + (((size_t)(t - 1) * 2 + d) * BB + bg * 32) * HH;
#pragma unroll
            for (int q = 0; q < 8; q++) {
                int idx = q * 256 + tid;
                int b = idx >> 6, k4 = idx & 63;
                float4 v = __ldcg((const float4*)(hsrc + b * HH + k4 * 4));
                *(float4*)(Hs + b * 288 + ((b >> 2) & 3) * 8 + k4 * 4) = v;
            }
            __syncthreads();

            u64t acc[3][4];
#pragma unroll
            for (int g = 0; g < 3; g++)
#pragma unroll
                for (int i = 0; i < 4; i++) acc[g][i] = 0ull;

#pragma unroll
            for (int k4 = 0; k4 < 16; k4++) {
                const float* wb = Ws + kh * 64 + k4 * 4;
                ulonglong2 w0 = *(const ulonglong2*)(wb + (jj) * 260);
                ulonglong2 w1 = *(const ulonglong2*)(wb + (8 + jj) * 260);
                ulonglong2 w2 = *(const ulonglong2*)(wb + (16 + jj) * 260);
#pragma unroll
                for (int i = 0; i < 4; i++) {
                    int b = bq * 4 + i;
                    ulonglong2 h = *(const ulonglong2*)(Hs + b * 288 +
                                       ((b >> 2) & 3) * 8 + kh * 64 + k4 * 4);
                    ffma2(acc[0][i], h.x, w0.x); ffma2(acc[0][i], h.y, w0.y);
                    ffma2(acc[1][i], h.x, w1.x); ffma2(acc[1][i], h.y, w1.y);
                    ffma2(acc[2][i], h.x, w2.x); ffma2(acc[2][i], h.y, w2.y);
                }
            }
#pragma unroll
            for (int g = 0; g < 3; g++)
#pragma unroll
                for (int i = 0; i < 4; i++) p[g * 4 + i] = hsum2(acc[g][i]);

            // kh reduction: everyone deposits, owners gather kh 1..3
            float* rs = Rs + ((size_t)kh * 64 + slot) * 12;
            *(float4*)(rs)     = make_float4(p[0], p[1], p[2], p[3]);
            *(float4*)(rs + 4) = make_float4(p[4], p[5], p[6], p[7]);
            *(float4*)(rs + 8) = make_float4(p[8], p[9], p[10], p[11]);
            __syncthreads();
            if (owner) {
#pragma unroll
                for (int kk = 1; kk < 4; kk++) {
                    const float* rr = Rs + ((size_t)kk * 64 + slot) * 12;
                    float4 a = *(const float4*)(rr);
                    float4 b4 = *(const float4*)(rr + 4);
                    float4 c4 = *(const float4*)(rr + 8);
                    p[0] += a.x;  p[1] += a.y;  p[2] += a.z;  p[3] += a.w;
                    p[4] += b4.x; p[5] += b4.y; p[6] += b4.z; p[7] += b4.w;
                    p[8] += c4.x; p[9] += c4.y; p[10] += c4.z; p[11] += c4.w;
                }
            }
        } else {
#pragma unroll
            for (int c = 0; c < 12; c++) p[c] = 0.f;
        }

        if (owner) {
#pragma unroll
            for (int i = 0; i < 4; i++) {
                float r = sigmoidf_(ir[i] + p[i] + bhr);
                float z = sigmoidf_(iz[i] + p[4 + i] + bhz);
                float n = tanhf_(in_[i] + r * (p[8 + i] + bhn));
                float hnew = (1.0f - z) * n + z * hprev[i];
                hprev[i] = hnew;
                __stcg(&hbuf[(((size_t)t * 2 + d) * BB + b0 + i) * HH + j], hnew);
                if (out && cap[i] == t) out[(size_t)(b0 + i) * 512 + d * 256 + j] = hnew;
            }
        }

        if (t < TT - 1) {
            if (owner) {
                // gi(t+1) prefetch overlaps the barrier spin (gi precomputed)
#pragma unroll
                for (int i = 0; i < 4; i++) {
                    const float* gp = gi + (((size_t)(t + 1) * 2 + d) * BB + b0 + i) * 768;
                    ir[i] = __ldcg(gp + j);
                    iz[i] = __ldcg(gp + 256 + j);
                    in_[i] = __ldcg(gp + 512 + j);
                }
            }
            group_bar(cnt, (unsigned)(t + 1) * GRP);
        }
    }
}

// ---------------------------------------------------------------------------
// Host launcher: graph-capturable (kernel launches + host-side func attr).
// Inputs (metadata order): input_tensor, W_ih0, W_hh0, b_ih0, b_hh0,
//                          W_ih1, W_hh1, b_ih1, b_hh1, seq_len
// ---------------------------------------------------------------------------
extern "C" void kernel_launch(void* const* d_in, const int* in_sizes, int n_in,
                              void* d_out, int out_size)
{
    (void)in_sizes; (void)n_in; (void)out_size;
    const float* x    = (const float*)d_in[0];
    const float* Wih0 = (const float*)d_in[1];
    const float* Whh0 = (const float*)d_in[2];
    const float* bih0 = (const float*)d_in[3];
    const float* bhh0 = (const float*)d_in[4];
    const float* Wih1 = (const float*)d_in[5];
    const float* Whh1 = (const float*)d_in[6];
    const float* bih1 = (const float*)d_in[7];
    const float* bhh1 = (const float*)d_in[8];
    const int*   seq  = (const int*)d_in[9];
    float* out = (float*)d_out;

    cudaFuncSetAttribute(k_rec, cudaFuncAttributeMaxDynamicSharedMemorySize,
                         SMEM_REC_BYTES);

    k_init<<<1, 32>>>();                                       // barrier reset
    k_gi0<<<dim3(TT, 32), 256>>>(x, Wih0, bih0);               // Phase A
    k_rec<<<NB, 256, SMEM_REC_BYTES>>>(Whh0, bhh0, 0, seq, (float*)0); // B
    k_gi1<<<dim3(TT, 16), 256>>>(Wih1, bih1);                  // Phase C
    k_rec<<<NB, 256, SMEM_REC_BYTES>>>(Whh1, bhh1, 1, seq, out);       // D
}

// round 17
// speedup vs baseline: 1.5520x; 1.1081x over previous
#include <cuda_runtime.h>
#include <math.h>

// ---------------------------------------------------------------------------
// EncoderRNN (2-layer, 2-"direction" forward GRU): B=64, T=1024, I=64, H=256
//
// Round-17 (from the passing R15; R16 never ran and contained a self-caught
// register-budget bug: u64 wreg[96] = 192 regs -> guaranteed spill):
//   k_rec: HALF-K W register cache: 48 u64 = 96 regs. k4 0..7 use W from
//          regs (4 h-LDS/k4); k4 8..15 from smem as R15 (7 LDS/k4).
//          Crossbar 3584 -> 2816 cyc/step. All indices identical to R15.
//   k_gi1: __launch_bounds__(256, 2) -> 2 CTAs/SM (R15: L1 63%, fma 46%,
//          issue 34%, occ 12.5% = latency-bound at 1 CTA/SM).
// Phases A-D, group barriers, packed FFMA2, approx gates: as Round 15.
// ---------------------------------------------------------------------------

#define TT 1024
#define BB 64
#define HH 256
#define NB 128   // persistent CTAs; <=148 SMs, co-resident by construction
#define GRP 32   // CTAs per barrier group (same direction + batch-half)

typedef unsigned long long u64t;

// k_rec dynamic smem partition (floats)
#define WS_F   (24 * 260)          // W tile, row stride 260 (4-float pad)
#define HS_F   (32 * 288 + 32)     // h tile, stride 288: 256 data + 32 pad >= skew 24
#define RS_F   (4 * 64 * 12)       // kh-partial reduction pane
#define SMEM_REC_BYTES ((WS_F + HS_F + RS_F) * 4)

// __device__ scratch (allocation-free rule: static device globals only)
__device__ float g_gi0[(size_t)TT * 2 * BB * 768];   // 402.7 MB
__device__ float g_gi1[(size_t)TT * 2 * BB * 768];   // 402.7 MB
__device__ float g_h0 [(size_t)TT * 2 * BB * HH];    // 134.2 MB
__device__ float g_h1 [(size_t)TT * 2 * BB * HH];    // 134.2 MB
__device__ unsigned g_cnt[2][4][32];                 // 128B-padded counters

__global__ void k_init() {                            // graph-replay reset
    if (threadIdx.x < 8) g_cnt[threadIdx.x >> 2][threadIdx.x & 3][0] = 0u;
}

// Packed fp32 FMA (B300 FFMA2 path; exact FFMA per lane).
__device__ __forceinline__ void ffma2(u64t& d, u64t a, u64t b) {
    asm("fma.rn.f32x2 %0, %1, %2, %0;" : "+l"(d) : "l"(a), "l"(b));
}
__device__ __forceinline__ float hsum2(u64t v) {
    return __uint_as_float((unsigned)v) + __uint_as_float((unsigned)(v >> 32));
}

__device__ __forceinline__ float sigmoidf_(float v) {
    return __fdividef(1.0f, 1.0f + __expf(-v));      // MUFU.EX2 + MUFU.RCP
}
__device__ __forceinline__ float tanhf_(float v) {
    float r;
    asm("tanh.approx.f32 %0, %1;" : "=f"(r) : "f"(v));
    return r;
}

__device__ __forceinline__ unsigned ld_acq(const unsigned* p) {
    unsigned v;
    asm volatile("ld.acquire.gpu.u32 %0, [%1];" : "=r"(v) : "l"(p) : "memory");
    return v;
}

// Software group barrier (release REDG / acquire-spin), validated R13/R15.
__device__ __forceinline__ void group_bar(unsigned* cnt, unsigned target) {
    __syncthreads();
    if (threadIdx.x == 0) {
        asm volatile("red.release.gpu.add.u32 [%0], %1;"
                     :: "l"(cnt), "r"(1u) : "memory");
        while (ld_acq(cnt) < target) {
            asm volatile("nanosleep.u32 32;");
        }
    }
    __syncthreads();
}

// ---------------------------------------------------------------------------
// Phase A: gi0 (K=64, small — unchanged, passing since R13).
// ---------------------------------------------------------------------------
__global__ __launch_bounds__(256) void k_gi0(const float* __restrict__ x,
                                             const float* __restrict__ Wih0,
                                             const float* __restrict__ bih0)
{
    __shared__ float Ws[48 * 68];
    __shared__ float Us[64 * 68];
    const int t  = blockIdx.x;
    const int d  = blockIdx.y >> 4;
    const int nt = blockIdx.y & 15;
    const int tid = threadIdx.x;
    const int jj = tid & 15, bq = tid >> 4;

#pragma unroll
    for (int i = 0; i < 3; i++) {
        int idx = i * 256 + tid;
        int r = idx >> 4, q = idx & 15;
        int grow = (r >> 4) * 256 + nt * 16 + (r & 15);
        *(float4*)(Ws + r * 68 + q * 4) =
            *(const float4*)(Wih0 + ((size_t)(d * 768 + grow)) * 64 + q * 4);
    }
#pragma unroll
    for (int i = 0; i < 4; i++) {
        int idx = i * 256 + tid;
        int bb = idx >> 4, q = idx & 15;
        *(float4*)(Us + bb * 68 + q * 4) =
            *(const float4*)(x + ((size_t)bb * TT + t) * 64 + q * 4);
    }
    __syncthreads();

    u64t acc[3][4];
#pragma unroll
    for (int g = 0; g < 3; g++)
#pragma unroll
        for (int i = 0; i < 4; i++) acc[g][i] = 0ull;

#pragma unroll
    for (int k4 = 0; k4 < 16; k4++) {
        ulonglong2 w0 = *(const ulonglong2*)(Ws + (jj) * 68 + k4 * 4);
        ulonglong2 w1 = *(const ulonglong2*)(Ws + (16 + jj) * 68 + k4 * 4);
        ulonglong2 w2 = *(const ulonglong2*)(Ws + (32 + jj) * 68 + k4 * 4);
#pragma unroll
        for (int i = 0; i < 4; i++) {
            ulonglong2 u = *(const ulonglong2*)(Us + (bq * 4 + i) * 68 + k4 * 4);
            ffma2(acc[0][i], u.x, w0.x); ffma2(acc[0][i], u.y, w0.y);
            ffma2(acc[1][i], u.x, w1.x); ffma2(acc[1][i], u.y, w1.y);
            ffma2(acc[2][i], u.x, w2.x); ffma2(acc[2][i], u.y, w2.y);
        }
    }

#pragma unroll
    for (int g = 0; g < 3; g++) {
        int row = g * 256 + nt * 16 + jj;
        float bias = bih0[d * 768 + row];
#pragma unroll
        for (int i = 0; i < 4; i++) {
            int b = bq * 4 + i;
            g_gi0[(((size_t)t * 2 + d) * BB + b) * 768 + row] = hsum2(acc[g][i]) + bias;
        }
    }
}

// ---------------------------------------------------------------------------
// Phase C: gi1. As R15 but minBlocksPerMultiprocessor = 2 (regs capped 128;
// loop-live set ~100 so expected spills are cold). Tile: 96 rows x 64 b,
// K=512 in 8 chunks; 8 batches/thread. Smem 43.6KB x 2 = 87KB/SM: fits.
// ---------------------------------------------------------------------------
__global__ __launch_bounds__(256, 2) void k_gi1(const float* __restrict__ Wih1,
                                                const float* __restrict__ bih1)
{
    __shared__ float Ws[96 * 68];        // 26,112 B
    __shared__ float Us[64 * 68 + 32];   // 17,536 B (skew room)
    const int t  = blockIdx.x;
    const int d  = blockIdx.y >> 3;
    const int nt = blockIdx.y & 7;
    const int tid = threadIdx.x;
    const int jj = tid & 31, bq = tid >> 5;

    u64t acc[3][8];
#pragma unroll
    for (int g = 0; g < 3; g++)
#pragma unroll
        for (int i = 0; i < 8; i++) acc[g][i] = 0ull;

    for (int c = 0; c < 8; c++) {
        __syncthreads();                 // previous chunk's reads done
#pragma unroll
        for (int q = 0; q < 6; q++) {
            int idx = q * 256 + tid;
            int r = idx >> 4, q4 = idx & 15;
            int grow = (r >> 5) * 256 + nt * 32 + (r & 31);
            *(float4*)(Ws + r * 68 + q4 * 4) =
                *(const float4*)(Wih1 + ((size_t)(d * 768 + grow)) * 512 + c * 64 + q4 * 4);
        }
        const int dd = c >> 2;
        const int koff = (c & 3) * 64;
#pragma unroll
        for (int q = 0; q < 4; q++) {
            int idx = q * 256 + tid;
            int b = idx >> 4, k4 = idx & 15;
            *(float4*)(Us + b * 68 + ((b >> 3) & 7) * 4 + k4 * 4) =
                *(const float4*)(g_h0 + (((size_t)t * 2 + dd) * BB + b) * HH + koff + k4 * 4);
        }
        __syncthreads();
#pragma unroll
        for (int k4 = 0; k4 < 16; k4++) {
            ulonglong2 w0 = *(const ulonglong2*)(Ws + (jj) * 68 + k4 * 4);
            ulonglong2 w1 = *(const ulonglong2*)(Ws + (32 + jj) * 68 + k4 * 4);
            ulonglong2 w2 = *(const ulonglong2*)(Ws + (64 + jj) * 68 + k4 * 4);
#pragma unroll
            for (int i = 0; i < 8; i++) {
                int b = bq * 8 + i;
                ulonglong2 u = *(const ulonglong2*)(Us + b * 68 + ((b >> 3) & 7) * 4 + k4 * 4);
                ffma2(acc[0][i], u.x, w0.x); ffma2(acc[0][i], u.y, w0.y);
                ffma2(acc[1][i], u.x, w1.x); ffma2(acc[1][i], u.y, w1.y);
                ffma2(acc[2][i], u.x, w2.x); ffma2(acc[2][i], u.y, w2.y);
            }
        }
    }

#pragma unroll
    for (int g = 0; g < 3; g++) {
        int row = g * 256 + nt * 32 + jj;
        float bias = bih1[d * 768 + row];
#pragma unroll
        for (int i = 0; i < 8; i++) {
            int b = bq * 8 + i;
            g_gi1[(((size_t)t * 2 + d) * BB + b) * 768 + row] = hsum2(acc[g][i]) + bias;
        }
    }
}

// ---------------------------------------------------------------------------
// Phases B/D: PERSISTENT recurrence, kh-split tile, HALF-K W register cache.
// Grid 128: d = bid>>6, js = (bid&63)>>1, bg = bid&1. Thread: jj = tid&7,
// bq = (tid>>3)&7, kh = tid>>6. Each thread: 3 gate rows x 4 batches x K/4.
// W slice for k4 0..7 (48 u64 = 96 regs) cached once; k4 8..15 read W from
// smem exactly as the passing R15. Hs stride 288 (no row overlap). Cross-kh
// reduction via Rs; owners (tid<64) do gates, stcg h-store, out-capture,
// gi(t+1) prefetch before the 32-CTA group barrier.
// ---------------------------------------------------------------------------
__global__ __launch_bounds__(256) void k_rec(const float* __restrict__ Whh,
                                             const float* __restrict__ bhh,
                                             int layer,
                                             const int* __restrict__ seq,
                                             float* __restrict__ out)
{
    extern __shared__ float sm[];
    float* Ws = sm;                      // 24 x 260
    float* Hs = sm + WS_F;               // 32 rows, stride 288 + skew
    float* Rs = sm + WS_F + HS_F;        // [kh][slot][12]

    const float* gi   = layer ? g_gi1 : g_gi0;
    float*       hbuf = layer ? g_h1  : g_h0;

    const int bid = blockIdx.x;
    const int d   = bid >> 6;
    const int rem = bid & 63;
    const int js  = rem >> 1;
    const int bg  = rem & 1;
    const int tid = threadIdx.x;
    const int jj  = tid & 7;
    const int bq  = (tid >> 3) & 7;
    const int kh  = tid >> 6;
    const int slot = tid & 63;
    const int j   = js * 8 + jj;
    const bool owner = (tid < 64);       // kh == 0
    const int b0  = bg * 32 + bq * 4;    // owner's first batch

    unsigned* cnt = &g_cnt[layer][d * 2 + bg][0];

    // Stage W tile once: 24 rows (3 gates x 8 j) x 256 K, stride 260.
#pragma unroll
    for (int i = 0; i < 6; i++) {
        int idx = i * 256 + tid;
        int r = idx >> 6, q = idx & 63;
        int grow = (r >> 3) * 256 + js * 8 + (r & 7);
        *(float4*)(Ws + r * 260 + q * 4) =
            *(const float4*)(Whh + ((size_t)(d * 768 + grow)) * HH + q * 4);
    }

    float bhr = 0.f, bhz = 0.f, bhn = 0.f;
    float hprev[4] = {0.f, 0.f, 0.f, 0.f};
    float ir[4], iz[4], in_[4];
    int cap[4] = {-1, -1, -1, -1};
    if (owner) {
        bhr = bhh[d * 768 + j];
        bhz = bhh[d * 768 + 256 + j];
        bhn = bhh[d * 768 + 512 + j];
#pragma unroll
        for (int i = 0; i < 4; i++) {
            if (out) {
                int s = seq[b0 + i] - 1;
                cap[i] = s < 0 ? 0 : (s > TT - 1 ? TT - 1 : s);
            }
            const float* gp = gi + (((size_t)d) * BB + b0 + i) * 768;  // t = 0
            ir[i] = __ldcg(gp + j);
            iz[i] = __ldcg(gp + 256 + j);
            in_[i] = __ldcg(gp + 512 + j);
        }
    }
    __syncthreads();

    // HALF-K W cache: rows {jj, 8+jj, 16+jj}, K sub-range [kh*64, kh*64+32).
    // wreg[r*16 + 2*p + half] = u64 pair of row r at k = p*4 + half*2.
    u64t wreg[48];                        // 96 registers
#pragma unroll
    for (int r = 0; r < 3; r++) {
#pragma unroll
        for (int p = 0; p < 8; p++) {
            ulonglong2 v = *(const ulonglong2*)(Ws + (r * 8 + jj) * 260 +
                                                kh * 64 + p * 4);
            wreg[r * 16 + p * 2]     = v.x;
            wreg[r * 16 + p * 2 + 1] = v.y;
        }
    }

    for (int t = 0; t < TT; t++) {
        float p[12];
        if (t > 0) {
            // stage full h(t-1) 32x256 (8 f4 per thread)
            const float* hsrc = hbuf + (((size_t)(t - 1) * 2 + d) * BB + bg * 32) * HH;
#pragma unroll
            for (int q = 0; q < 8; q++) {
                int idx = q * 256 + tid;
                int b = idx >> 6, k4 = idx & 63;
                float4 v = __ldcg((const float4*)(hsrc + b * HH + k4 * 4));
                *(float4*)(Hs + b * 288 + ((b >> 2) & 3) * 8 + k4 * 4) = v;
            }
            __syncthreads();

            u64t acc[3][4];
#pragma unroll
            for (int g = 0; g < 3; g++)
#pragma unroll
                for (int i = 0; i < 4; i++) acc[g][i] = 0ull;

            // k4 0..7: W from registers (4 h-LDS per k4)
#pragma unroll
            for (int k4 = 0; k4 < 8; k4++) {
                u64t w0a = wreg[k4 * 2],      w0b = wreg[k4 * 2 + 1];
                u64t w1a = wreg[16 + k4 * 2], w1b = wreg[16 + k4 * 2 + 1];
                u64t w2a = wreg[32 + k4 * 2], w2b = wreg[32 + k4 * 2 + 1];
#pragma unroll
                for (int i = 0; i < 4; i++) {
                    int b = bq * 4 + i;
                    ulonglong2 h = *(const ulonglong2*)(Hs + b * 288 +
                                       ((b >> 2) & 3) * 8 + kh * 64 + k4 * 4);
                    ffma2(acc[0][i], h.x, w0a); ffma2(acc[0][i], h.y, w0b);
                    ffma2(acc[1][i], h.x, w1a); ffma2(acc[1][i], h.y, w1b);
                    ffma2(acc[2][i], h.x, w2a); ffma2(acc[2][i], h.y, w2b);
                }
            }
            // k4 8..15: W from smem (exactly as the passing R15)
#pragma unroll
            for (int k4 = 8; k4 < 16; k4++) {
                const float* wb = Ws + kh * 64 + k4 * 4;
                ulonglong2 w0 = *(const ulonglong2*)(wb + (jj) * 260);
                ulonglong2 w1 = *(const ulonglong2*)(wb + (8 + jj) * 260);
                ulonglong2 w2 = *(const ulonglong2*)(wb + (16 + jj) * 260);
#pragma unroll
                for (int i = 0; i < 4; i++) {
                    int b = bq * 4 + i;
                    ulonglong2 h = *(const ulonglong2*)(Hs + b * 288 +
                                       ((b >> 2) & 3) * 8 + kh * 64 + k4 * 4);
                    ffma2(acc[0][i], h.x, w0.x); ffma2(acc[0][i], h.y, w0.y);
                    ffma2(acc[1][i], h.x, w1.x); ffma2(acc[1][i], h.y, w1.y);
                    ffma2(acc[2][i], h.x, w2.x); ffma2(acc[2][i], h.y, w2.y);
                }
            }
#pragma unroll
            for (int g = 0; g < 3; g++)
#pragma unroll
                for (int i = 0; i < 4; i++) p[g * 4 + i] = hsum2(acc[g][i]);

            // kh reduction: everyone deposits, owners gather kh 1..3
            float* rs = Rs + ((size_t)kh * 64 + slot) * 12;
            *(float4*)(rs)     = make_float4(p[0], p[1], p[2], p[3]);
            *(float4*)(rs + 4) = make_float4(p[4], p[5], p[6], p[7]);
            *(float4*)(rs + 8) = make_float4(p[8], p[9], p[10], p[11]);
            __syncthreads();
            if (owner) {
#pragma unroll
                for (int kk = 1; kk < 4; kk++) {
                    const float* rr = Rs + ((size_t)kk * 64 + slot) * 12;
                    float4 a = *(const float4*)(rr);
                    float4 b4 = *(const float4*)(rr + 4);
                    float4 c4 = *(const float4*)(rr + 8);
                    p[0] += a.x;  p[1] += a.y;  p[2] += a.z;  p[3] += a.w;
                    p[4] += b4.x; p[5] += b4.y; p[6] += b4.z; p[7] += b4.w;
                    p[8] += c4.x; p[9] += c4.y; p[10] += c4.z; p[11] += c4.w;
                }
            }
        } else {
#pragma unroll
            for (int c = 0; c < 12; c++) p[c] = 0.f;
        }

        if (owner) {
#pragma unroll
            for (int i = 0; i < 4; i++) {
                float r = sigmoidf_(ir[i] + p[i] + bhr);
                float z = sigmoidf_(iz[i] + p[4 + i] + bhz);
                float n = tanhf_(in_[i] + r * (p[8 + i] + bhn));
                float hnew = (1.0f - z) * n + z * hprev[i];
                hprev[i] = hnew;
                __stcg(&hbuf[(((size_t)t * 2 + d) * BB + b0 + i) * HH + j], hnew);
                if (out && cap[i] == t) out[(size_t)(b0 + i) * 512 + d * 256 + j] = hnew;
            }
        }

        if (t < TT - 1) {
            if (owner) {
                // gi(t+1) prefetch overlaps the barrier spin (gi precomputed)
#pragma unroll
                for (int i = 0; i < 4; i++) {
                    const float* gp = gi + (((size_t)(t + 1) * 2 + d) * BB + b0 + i) * 768;
                    ir[i] = __ldcg(gp + j);
                    iz[i] = __ldcg(gp + 256 + j);
                    in_[i] = __ldcg(gp + 512 + j);
                }
            }
            group_bar(cnt, (unsigned)(t + 1) * GRP);
        }
    }
}

// ---------------------------------------------------------------------------
// Host launcher: graph-capturable (kernel launches + host-side func attr).
// Inputs (metadata order): input_tensor, W_ih0, W_hh0, b_ih0, b_hh0,
//                          W_ih1, W_hh1, b_ih1, b_hh1, seq_len
// ---------------------------------------------------------------------------
extern "C" void kernel_launch(void* const* d_in, const int* in_sizes, int n_in,
                              void* d_out, int out_size)
{
    (void)in_sizes; (void)n_in; (void)out_size;
    const float* x    = (const float*)d_in[0];
    const float* Wih0 = (const float*)d_in[1];
    const float* Whh0 = (const float*)d_in[2];
    const float* bih0 = (const float*)d_in[3];
    const float* bhh0 = (const float*)d_in[4];
    const float* Wih1 = (const float*)d_in[5];
    const float* Whh1 = (const float*)d_in[6];
    const float* bih1 = (const float*)d_in[7];
    const float* bhh1 = (const float*)d_in[8];
    const int*   seq  = (const int*)d_in[9];
    float* out = (float*)d_out;

    cudaFuncSetAttribute(k_rec, cudaFuncAttributeMaxDynamicSharedMemorySize,
                         SMEM_REC_BYTES);

    k_init<<<1, 32>>>();                                       // barrier reset
    k_gi0<<<dim3(TT, 32), 256>>>(x, Wih0, bih0);               // Phase A
    k_rec<<<NB, 256, SMEM_REC_BYTES>>>(Whh0, bhh0, 0, seq, (float*)0); // B
    k_gi1<<<dim3(TT, 16), 256>>>(Wih1, bih1);                  // Phase C
    k_rec<<<NB, 256, SMEM_REC_BYTES>>>(Whh1, bhh1, 1, seq, out);       // D
}